// round 16
// baseline (speedup 1.0000x reference)
#include <cuda_runtime.h>
#include <cuda_fp16.h>
#include <math.h>
#include <stdint.h>

#define TOK   4096
#define NSEQ  2048
#define DIM   768
#define H3    2304
#define HID   3072
#define NHEAD 12
#define HD    64

__device__ __align__(128) __half g_h  [TOK * DIM];
__device__ __align__(128) __half g_qkv[TOK * H3];
__device__ __align__(128) __half g_o  [TOK * DIM];
__device__ __align__(128) float  g_x1 [TOK * DIM];
__device__ __align__(128) __half g_h2 [TOK * DIM];
__device__ __align__(128) __half g_m  [TOK * HID];
__device__ __align__(128) __half g_wq [H3 * DIM];
__device__ __align__(128) __half g_wp [DIM * DIM];
__device__ __align__(128) __half g_w1 [HID * DIM];
__device__ __align__(128) __half g_w2 [DIM * HID];

// ---------------- PTX helpers ----------------
__device__ __forceinline__ void mma_f16(float* d,
    uint32_t a0, uint32_t a1, uint32_t a2, uint32_t a3, uint32_t b0, uint32_t b1)
{
    asm volatile(
        "mma.sync.aligned.m16n8k16.row.col.f32.f16.f16.f32 "
        "{%0,%1,%2,%3}, {%4,%5,%6,%7}, {%8,%9}, {%0,%1,%2,%3};"
        : "+f"(d[0]), "+f"(d[1]), "+f"(d[2]), "+f"(d[3])
        : "r"(a0), "r"(a1), "r"(a2), "r"(a3), "r"(b0), "r"(b1));
}
__device__ __forceinline__ void cp_async16(uint32_t s, const void* g) {
    asm volatile("cp.async.cg.shared.global [%0], [%1], 16;" :: "r"(s), "l"(g));
}
__device__ __forceinline__ void cp_commit() { asm volatile("cp.async.commit_group;" ::); }
template<int N> __device__ __forceinline__ void cp_wait() {
    asm volatile("cp.async.wait_group %0;" :: "n"(N));
}
__device__ __forceinline__ uint32_t smem_u32(const void* p) {
    uint32_t a;
    asm("{ .reg .u64 t; cvta.to.shared.u64 t, %1; cvt.u32.u64 %0, t; }" : "=r"(a) : "l"(p));
    return a;
}
__device__ __forceinline__ uint32_t h2u(float x, float y) {
    __half2 h = __floats2half2_rn(x, y);
    return *(uint32_t*)&h;
}
__device__ __forceinline__ float ex2(float x) {
    float y; asm("ex2.approx.f32 %0, %1;" : "=f"(y) : "f"(x)); return y;
}
__device__ __forceinline__ void ldsm_x4(
    uint32_t& r0, uint32_t& r1, uint32_t& r2, uint32_t& r3, uint32_t a)
{
    asm volatile("ldmatrix.sync.aligned.m8n8.x4.shared.b16 {%0,%1,%2,%3}, [%4];"
                 : "=r"(r0), "=r"(r1), "=r"(r2), "=r"(r3) : "r"(a));
}
__device__ __forceinline__ void ldsm_x4_t(
    uint32_t& r0, uint32_t& r1, uint32_t& r2, uint32_t& r3, uint32_t a)
{
    asm volatile("ldmatrix.sync.aligned.m8n8.x4.trans.shared.b16 {%0,%1,%2,%3}, [%4];"
                 : "=r"(r0), "=r"(r1), "=r"(r2), "=r"(r3) : "r"(a));
}

// -------- merged preamble: weight transpose (4 weights) + LN1, one launch --------
#define TRW_B0 (72 * 24)
#define TRW_B1 (24 * 24)
#define TRW_B2 (96 * 24)
#define TRW_B3 (24 * 96)
#define TRW_TOTAL (TRW_B0 + TRW_B1 + TRW_B2 + TRW_B3)
#define PRE_TOTAL (TRW_TOTAL + TOK)

__global__ __launch_bounds__(256) void preamble_kernel(
    const float* __restrict__ s0, __half* __restrict__ d0,
    const float* __restrict__ s1, __half* __restrict__ d1,
    const float* __restrict__ s2, __half* __restrict__ d2,
    const float* __restrict__ s3, __half* __restrict__ d3,
    const float* __restrict__ x,  const float* __restrict__ lg,
    const float* __restrict__ lb, __half* __restrict__ lout)
{
    int blk = blockIdx.x;
    if (blk >= TRW_TOTAL) {
        int row = blk - TRW_TOTAL, t = threadIdx.x;
        const float* xr = x + row * DIM;
        float v0 = xr[t], v1 = xr[t + 256], v2 = xr[t + 512];
        float s = v0 + v1 + v2, q = v0 * v0 + v1 * v1 + v2 * v2;
        __shared__ float rs[8], rq[8];
        #pragma unroll
        for (int o = 16; o; o >>= 1) {
            s += __shfl_xor_sync(0xffffffffu, s, o);
            q += __shfl_xor_sync(0xffffffffu, q, o);
        }
        if ((t & 31) == 0) { rs[t >> 5] = s; rq[t >> 5] = q; }
        __syncthreads();
        __shared__ float smu, srstd;
        if (t == 0) {
            float S = 0.f, Q = 0.f;
            #pragma unroll
            for (int i = 0; i < 8; i++) { S += rs[i]; Q += rq[i]; }
            float mu = S * (1.0f / DIM), var = Q * (1.0f / DIM) - mu * mu;
            smu = mu; srstd = rsqrtf(var + 1e-5f);
        }
        __syncthreads();
        float mu = smu, r = srstd;
        __half* orow = lout + row * DIM;
        orow[t]       = __float2half((v0 - mu) * r * lg[t]       + lb[t]);
        orow[t + 256] = __float2half((v1 - mu) * r * lg[t + 256] + lb[t + 256]);
        orow[t + 512] = __float2half((v2 - mu) * r * lg[t + 512] + lb[t + 512]);
        return;
    }
    const float* src; __half* dst; int K, N, lbk;
    if (blk < TRW_B0)                       { src = s0; dst = d0; K = DIM; N = H3;  lbk = blk; }
    else if (blk < TRW_B0 + TRW_B1)         { src = s1; dst = d1; K = DIM; N = DIM; lbk = blk - TRW_B0; }
    else if (blk < TRW_B0 + TRW_B1 + TRW_B2){ src = s2; dst = d2; K = DIM; N = HID; lbk = blk - TRW_B0 - TRW_B1; }
    else                                    { src = s3; dst = d3; K = HID; N = DIM; lbk = blk - TRW_B0 - TRW_B1 - TRW_B2; }
    int nblk = N / 32;
    int nb = (lbk % nblk) * 32, kb = (lbk / nblk) * 32;

    __shared__ float t[32][33];
    int tx = threadIdx.x & 31, ty = threadIdx.x >> 5;
    #pragma unroll
    for (int i = 0; i < 32; i += 8)
        t[ty + i][tx] = src[(size_t)(kb + ty + i) * N + nb + tx];
    __syncthreads();
    #pragma unroll
    for (int i = 0; i < 32; i += 8)
        dst[(size_t)(nb + ty + i) * K + kb + tx] = __float2half(t[tx][ty + i]);
}

// -------- LayerNorm (fp16 out) --------
__global__ __launch_bounds__(256) void ln_kernel(
    const float* __restrict__ x, const float* __restrict__ g,
    const float* __restrict__ b, __half* __restrict__ out)
{
    int row = blockIdx.x, t = threadIdx.x;
    const float* xr = x + row * DIM;
    float v0 = xr[t], v1 = xr[t + 256], v2 = xr[t + 512];
    float s = v0 + v1 + v2, q = v0 * v0 + v1 * v1 + v2 * v2;
    __shared__ float rs[8], rq[8];
    #pragma unroll
    for (int o = 16; o; o >>= 1) {
        s += __shfl_xor_sync(0xffffffffu, s, o);
        q += __shfl_xor_sync(0xffffffffu, q, o);
    }
    if ((t & 31) == 0) { rs[t >> 5] = s; rq[t >> 5] = q; }
    __syncthreads();
    __shared__ float smu, srstd;
    if (t == 0) {
        float S = 0.f, Q = 0.f;
        #pragma unroll
        for (int i = 0; i < 8; i++) { S += rs[i]; Q += rq[i]; }
        float mu = S * (1.0f / DIM), var = Q * (1.0f / DIM) - mu * mu;
        smu = mu; srstd = rsqrtf(var + 1e-5f);
    }
    __syncthreads();
    float mu = smu, r = srstd;
    __half* orow = out + row * DIM;
    orow[t]       = __float2half((v0 - mu) * r * g[t]       + b[t]);
    orow[t + 256] = __float2half((v1 - mu) * r * g[t + 256] + b[t + 256]);
    orow[t + 512] = __float2half((v2 - mu) * r * g[t + 512] + b[t + 512]);
}

// -------- fp16 tensor-core GEMM: C = A[M,K] @ BT[N,K]^T (+epilogue) --------
// BM x BN CTA tile, 128 threads = 4 warps (2x2), warp tile (BM/2) x (BN/2).
// ldmatrix.x4 fetch, 3-stage cp.async pipeline.
#define HST 40
#define HSTAGES 3
#define HSMEM_OF(BM, BN) (HSTAGES * ((BM) + (BN)) * HST * 2)

template<int EPI, typename OT, int BM, int BN>
__global__ __launch_bounds__(128) void gemm_h(
    const __half* __restrict__ A, const __half* __restrict__ BT,
    const float* __restrict__ bias, const float* __restrict__ res,
    OT* __restrict__ C, int M, int N, int K)
{
    constexpr int MI = BM / 32;                    // 16-row m-frags per warp
    constexpr int NF = BN / 16;                    // 8-col n-frags per warp
    constexpr int ATILE_B = BM * HST * 2;
    constexpr int BTILE_B = BN * HST * 2;
    constexpr int STAGE_B = ATILE_B + BTILE_B;

    extern __shared__ char smem[];
    uint32_t sb = smem_u32(smem);

    int tid = threadIdx.x, lane = tid & 31, warp = tid >> 5;
    int wm = warp >> 1, wn = warp & 1;
    int gq = lane >> 2, gt = lane & 3;
    int row0 = blockIdx.y * BM, col0 = blockIdx.x * BN;

    int lrow = lane & 7;
    int lmid = (lane >> 3) & 1;
    int lhi  = lane >> 4;
    int a_row = lrow + 8 * lmid;
    int a_c8  = lhi;
    int b_row = lrow + 8 * lhi;
    int b_c8  = lmid;

    float acc[MI][NF][4];
    #pragma unroll
    for (int mi = 0; mi < MI; mi++)
        #pragma unroll
        for (int nf = 0; nf < NF; nf++)
            #pragma unroll
            for (int j = 0; j < 4; j++) acc[mi][nf][j] = 0.f;

    auto load_tile = [&](int kt, int buf) {
        uint32_t ab = sb + buf * STAGE_B;
        int k0 = kt * 32;
        #pragma unroll
        for (int i = 0; i < BM / 32; i++) {
            int e = tid + i * 128;
            int r = e >> 2, c8 = e & 3;
            cp_async16(ab + r * (HST * 2) + c8 * 16,
                       A + (size_t)(row0 + r) * K + k0 + c8 * 8);
        }
        #pragma unroll
        for (int i = 0; i < BN / 32; i++) {
            int e = tid + i * 128;
            int r = e >> 2, c8 = e & 3;
            cp_async16(ab + ATILE_B + r * (HST * 2) + c8 * 16,
                       BT + (size_t)(col0 + r) * K + k0 + c8 * 8);
        }
        cp_commit();
    };

    int nt = K / 32;
    load_tile(0, 0);
    load_tile(1, 1);

    for (int t = 0; t < nt; t++) {
        cp_wait<HSTAGES - 2>();
        __syncthreads();
        if (t + 2 < nt) load_tile(t + 2, (t + 2) % HSTAGES);
        int buf = t % HSTAGES;

        uint32_t Ab = sb + buf * STAGE_B;
        uint32_t Bb = Ab + ATILE_B;

        #pragma unroll
        for (int ks = 0; ks < 2; ks++) {
            int kh = ks * 16;
            uint32_t af[MI][4];
            #pragma unroll
            for (int mi = 0; mi < MI; mi++) {
                uint32_t addr = Ab + ((wm * (BM / 2) + mi * 16 + a_row) * HST + kh + a_c8 * 8) * 2;
                ldsm_x4(af[mi][0], af[mi][1], af[mi][2], af[mi][3], addr);
            }
            uint32_t bf[NF][2];
            #pragma unroll
            for (int p = 0; p < NF / 2; p++) {
                uint32_t addr = Bb + ((wn * (BN / 2) + p * 16 + b_row) * HST + kh + b_c8 * 8) * 2;
                ldsm_x4(bf[2 * p][0], bf[2 * p][1], bf[2 * p + 1][0], bf[2 * p + 1][1], addr);
            }
            #pragma unroll
            for (int mi = 0; mi < MI; mi++)
                #pragma unroll
                for (int nf = 0; nf < NF; nf++)
                    mma_f16(acc[mi][nf],
                            af[mi][0], af[mi][1], af[mi][2], af[mi][3],
                            bf[nf][0], bf[nf][1]);
        }
    }

    #pragma unroll
    for (int mi = 0; mi < MI; mi++) {
        int r = row0 + wm * (BM / 2) + mi * 16 + gq;
        #pragma unroll
        for (int nf = 0; nf < NF; nf++) {
            int c = col0 + wn * (BN / 2) + nf * 8 + gt * 2;
            float v0 = acc[mi][nf][0], v1 = acc[mi][nf][1];
            float v2 = acc[mi][nf][2], v3 = acc[mi][nf][3];
            if (EPI >= 1) {
                float b0 = bias[c], b1 = bias[c + 1];
                v0 += b0; v1 += b1; v2 += b0; v3 += b1;
            }
            if (EPI == 1) {
                const float2 r01 = *(const float2*)&res[(size_t) r      * N + c];
                const float2 r23 = *(const float2*)&res[(size_t)(r + 8) * N + c];
                v0 += r01.x; v1 += r01.y; v2 += r23.x; v3 += r23.y;
            }
            if (EPI == 2) {
                v0 = 0.5f * v0 * (1.0f + erff(v0 * 0.70710678118f));
                v1 = 0.5f * v1 * (1.0f + erff(v1 * 0.70710678118f));
                v2 = 0.5f * v2 * (1.0f + erff(v2 * 0.70710678118f));
                v3 = 0.5f * v3 * (1.0f + erff(v3 * 0.70710678118f));
            }
            if constexpr (sizeof(OT) == 2) {
                __half* Ch = (__half*)C;
                *(__half2*)&Ch[(size_t) r      * N + c] = __floats2half2_rn(v0, v1);
                *(__half2*)&Ch[(size_t)(r + 8) * N + c] = __floats2half2_rn(v2, v3);
            } else {
                float* Cf = (float*)C;
                *(float2*)&Cf[(size_t) r      * N + c] = make_float2(v0, v1);
                *(float2*)&Cf[(size_t)(r + 8) * N + c] = make_float2(v2, v3);
            }
        }
    }
}

// -------- fp16 flash attention (unchanged from R15) --------
#define KVH (64 * 72)
#define QHS (128 * 72)
#define ATTN_SMEM_B ((QHS + 6 * KVH) * 2)

__global__ __launch_bounds__(256) void attn_h(
    const __half* __restrict__ qkv, __half* __restrict__ o)
{
    extern __shared__ __half smh[];
    __half* Qs = smh;
    __half* Ks = smh + QHS;
    __half* Vs = smh + QHS + 3 * KVH;

    int tid = threadIdx.x, lane = tid & 31, warp = tid >> 5;
    int gq = lane >> 2, gt = lane & 3, wr = warp * 16;
    int lrow = lane & 7, lsel = (lane >> 3) & 1, lhi = lane >> 4;
    int qt = blockIdx.x, h = blockIdx.y, b = blockIdx.z;
    int q_tok0 = b * NSEQ + qt * 128;
    int qcol = h * HD, kcol = DIM + h * HD, vcol = 2 * DIM + h * HD;

    auto load_kv = [&](int kt, int buf) {
        int k_tok0 = b * NSEQ + kt * 64;
        #pragma unroll
        for (int i = 0; i < 2; i++) {
            int e = tid + i * 256;
            int r = e >> 3, c = e & 7;
            cp_async16(smem_u32(&Ks[buf * KVH + r * 72 + c * 8]),
                       qkv + (size_t)(k_tok0 + r) * H3 + kcol + c * 8);
            cp_async16(smem_u32(&Vs[buf * KVH + r * 72 + c * 8]),
                       qkv + (size_t)(k_tok0 + r) * H3 + vcol + c * 8);
        }
        cp_commit();
    };

    #pragma unroll
    for (int i = 0; i < 4; i++) {
        int e = tid + i * 256;
        int r = e >> 3, c = e & 7;
        cp_async16(smem_u32(&Qs[r * 72 + c * 8]),
                   qkv + (size_t)(q_tok0 + r) * H3 + qcol + c * 8);
    }
    cp_commit();
    load_kv(0, 0);
    cp_wait<1>();
    __syncthreads();

    const uint32_t* Qu = (const uint32_t*)Qs;
    __half2 hs = __half2half2(__float2half(0.125f * 1.44269504f));
    uint32_t qf[4][4];
    #pragma unroll
    for (int ks = 0; ks < 4; ks++) {
        #pragma unroll
        for (int j = 0; j < 4; j++) {
            int r = wr + gq + (j & 1) * 8;
            int cw = 8 * ks + gt + (j >> 1) * 4;
            __half2 v = *(__half2*)&Qu[r * 36 + cw];
            v = __hmul2(v, hs);
            qf[ks][j] = *(uint32_t*)&v;
        }
    }
    load_kv(1, 1);

    uint32_t kbase[4], vbase[4];
    #pragma unroll
    for (int p = 0; p < 4; p++) {
        kbase[p] = smem_u32(&Ks[(p * 16 + lhi * 8 + lrow) * 72 + lsel * 8]);
        vbase[p] = smem_u32(&Vs[(lsel * 8 + lrow) * 72 + p * 16 + lhi * 8]);
    }

    float m0 = -1e30f, m1 = -1e30f, l0 = 0.f, l1 = 0.f;
    float oacc[8][4];
    #pragma unroll
    for (int nf = 0; nf < 8; nf++)
        #pragma unroll
        for (int j = 0; j < 4; j++) oacc[nf][j] = 0.f;

    const int nkt = NSEQ / 64;
    for (int kt = 0; kt < nkt; kt++) {
        cp_wait<1>();
        __syncthreads();
        if (kt + 2 < nkt) load_kv(kt + 2, (kt + 2) % 3);
        uint32_t boff = (uint32_t)((kt % 3) * KVH * 2);

        float sacc[8][4];
        #pragma unroll
        for (int nf = 0; nf < 8; nf++)
            #pragma unroll
            for (int j = 0; j < 4; j++) sacc[nf][j] = 0.f;
        #pragma unroll
        for (int ks = 0; ks < 4; ks++) {
            #pragma unroll
            for (int nfp = 0; nfp < 4; nfp++) {
                uint32_t b0, b1, b2, b3;
                ldsm_x4(b0, b1, b2, b3, kbase[nfp] + boff + ks * 32);
                mma_f16(sacc[2 * nfp],     qf[ks][0], qf[ks][1], qf[ks][2], qf[ks][3], b0, b1);
                mma_f16(sacc[2 * nfp + 1], qf[ks][0], qf[ks][1], qf[ks][2], qf[ks][3], b2, b3);
            }
        }

        float mx0 = -1e30f, mx1 = -1e30f;
        #pragma unroll
        for (int nf = 0; nf < 8; nf++) {
            mx0 = fmaxf(mx0, fmaxf(sacc[nf][0], sacc[nf][1]));
            mx1 = fmaxf(mx1, fmaxf(sacc[nf][2], sacc[nf][3]));
        }
        mx0 = fmaxf(mx0, __shfl_xor_sync(0xffffffffu, mx0, 1));
        mx0 = fmaxf(mx0, __shfl_xor_sync(0xffffffffu, mx0, 2));
        mx1 = fmaxf(mx1, __shfl_xor_sync(0xffffffffu, mx1, 1));
        mx1 = fmaxf(mx1, __shfl_xor_sync(0xffffffffu, mx1, 2));
        float mn0 = fmaxf(m0, mx0), mn1 = fmaxf(m1, mx1);
        float alpha0 = ex2(m0 - mn0), alpha1 = ex2(m1 - mn1);
        m0 = mn0; m1 = mn1;

        float sum0 = 0.f, sum1 = 0.f;
        #pragma unroll
        for (int nf = 0; nf < 8; nf++) {
            sacc[nf][0] = ex2(sacc[nf][0] - mn0);
            sacc[nf][1] = ex2(sacc[nf][1] - mn0);
            sacc[nf][2] = ex2(sacc[nf][2] - mn1);
            sacc[nf][3] = ex2(sacc[nf][3] - mn1);
            sum0 += sacc[nf][0] + sacc[nf][1];
            sum1 += sacc[nf][2] + sacc[nf][3];
        }
        sum0 += __shfl_xor_sync(0xffffffffu, sum0, 1);
        sum0 += __shfl_xor_sync(0xffffffffu, sum0, 2);
        sum1 += __shfl_xor_sync(0xffffffffu, sum1, 1);
        sum1 += __shfl_xor_sync(0xffffffffu, sum1, 2);
        l0 = l0 * alpha0 + sum0;
        l1 = l1 * alpha1 + sum1;

        if (!__all_sync(0xffffffffu, (alpha0 == 1.0f) & (alpha1 == 1.0f))) {
            #pragma unroll
            for (int nf = 0; nf < 8; nf++) {
                oacc[nf][0] *= alpha0; oacc[nf][1] *= alpha0;
                oacc[nf][2] *= alpha1; oacc[nf][3] *= alpha1;
            }
        }

        #pragma unroll
        for (int j = 0; j < 4; j++) {
            uint32_t a0 = h2u(sacc[2 * j    ][0], sacc[2 * j    ][1]);
            uint32_t a1 = h2u(sacc[2 * j    ][2], sacc[2 * j    ][3]);
            uint32_t a2 = h2u(sacc[2 * j + 1][0], sacc[2 * j + 1][1]);
            uint32_t a3 = h2u(sacc[2 * j + 1][2], sacc[2 * j + 1][3]);
            #pragma unroll
            for (int nfp = 0; nfp < 4; nfp++) {
                uint32_t b0, b1, b2, b3;
                ldsm_x4_t(b0, b1, b2, b3, vbase[nfp] + boff + j * 2304);
                mma_f16(oacc[2 * nfp],     a0, a1, a2, a3, b0, b1);
                mma_f16(oacc[2 * nfp + 1], a0, a1, a2, a3, b2, b3);
            }
        }
    }

    float invl0 = 1.0f / l0, invl1 = 1.0f / l1;
    int r0 = q_tok0 + wr + gq;
    #pragma unroll
    for (int nf = 0; nf < 8; nf++) {
        int c = h * HD + nf * 8 + gt * 2;
        *(__half2*)&o[(size_t) r0      * DIM + c] =
            __floats2half2_rn(oacc[nf][0] * invl0, oacc[nf][1] * invl0);
        *(__half2*)&o[(size_t)(r0 + 8) * DIM + c] =
            __floats2half2_rn(oacc[nf][2] * invl1, oacc[nf][3] * invl1);
    }
}

// ---------------- Launch ----------------
extern "C" void kernel_launch(void* const* d_in, const int* in_sizes, int n_in,
                              void* d_out, int out_size)
{
    const float* x      = (const float*)d_in[0];
    const float* ln1_g  = (const float*)d_in[1];
    const float* ln1_b  = (const float*)d_in[2];
    const float* w_qkv  = (const float*)d_in[3];
    const float* w_proj = (const float*)d_in[4];
    const float* b_proj = (const float*)d_in[5];
    const float* ln2_g  = (const float*)d_in[6];
    const float* ln2_b  = (const float*)d_in[7];
    const float* w_fc1  = (const float*)d_in[8];
    const float* b_fc1  = (const float*)d_in[9];
    const float* w_fc2  = (const float*)d_in[10];
    const float* b_fc2  = (const float*)d_in[11];
    float* out = (float*)d_out;

    __half *p_h, *p_qkv, *p_o, *p_h2, *p_m, *p_wq, *p_wp, *p_w1, *p_w2;
    float  *p_x1;
    cudaGetSymbolAddress((void**)&p_h,   g_h);
    cudaGetSymbolAddress((void**)&p_qkv, g_qkv);
    cudaGetSymbolAddress((void**)&p_o,   g_o);
    cudaGetSymbolAddress((void**)&p_x1,  g_x1);
    cudaGetSymbolAddress((void**)&p_h2,  g_h2);
    cudaGetSymbolAddress((void**)&p_m,   g_m);
    cudaGetSymbolAddress((void**)&p_wq,  g_wq);
    cudaGetSymbolAddress((void**)&p_wp,  g_wp);
    cudaGetSymbolAddress((void**)&p_w1,  g_w1);
    cudaGetSymbolAddress((void**)&p_w2,  g_w2);

    cudaFuncSetAttribute(attn_h, cudaFuncAttributeMaxDynamicSharedMemorySize, ATTN_SMEM_B);
    cudaFuncSetAttribute((gemm_h<0, __half, 128, 128>), cudaFuncAttributeMaxDynamicSharedMemorySize, HSMEM_OF(128, 128));
    cudaFuncSetAttribute((gemm_h<2, __half, 128, 128>), cudaFuncAttributeMaxDynamicSharedMemorySize, HSMEM_OF(128, 128));
    cudaFuncSetAttribute((gemm_h<1, float, 64, 64>),    cudaFuncAttributeMaxDynamicSharedMemorySize, HSMEM_OF(64, 64));

    // 0. preamble: weight transpose + LN1 (one launch)
    preamble_kernel<<<PRE_TOTAL, 256>>>(w_qkv, p_wq, w_proj, p_wp,
                                        w_fc1, p_w1, w_fc2, p_w2,
                                        x, ln1_g, ln1_b, p_h);
    // 2. QKV GEMM (128x128)
    gemm_h<0, __half, 128, 128><<<dim3(H3 / 128, TOK / 128), 128, HSMEM_OF(128, 128)>>>(
        p_h, p_wq, nullptr, nullptr, p_qkv, TOK, H3, DIM);
    // 3. Attention
    attn_h<<<dim3(NSEQ / 128, NHEAD, 2), 256, ATTN_SMEM_B>>>(p_qkv, p_o);
    // 4. Proj + bias + residual(x) -> fp32 (64x64: 768 CTAs)
    gemm_h<1, float, 64, 64><<<dim3(DIM / 64, TOK / 64), 128, HSMEM_OF(64, 64)>>>(
        p_o, p_wp, b_proj, x, p_x1, TOK, DIM, DIM);
    // 5. LN2 -> fp16
    ln_kernel<<<TOK, 256>>>(p_x1, ln2_g, ln2_b, p_h2);
    // 6. FC1 + bias + GELU -> fp16 (128x128)
    gemm_h<2, __half, 128, 128><<<dim3(HID / 128, TOK / 128), 128, HSMEM_OF(128, 128)>>>(
        p_h2, p_w1, b_fc1, nullptr, p_m, TOK, HID, DIM);
    // 7. FC2 + bias + residual(x1) -> out (64x64: 768 CTAs)
    gemm_h<1, float, 64, 64><<<dim3(DIM / 64, TOK / 64), 128, HSMEM_OF(64, 64)>>>(
        p_m, p_w2, b_fc2, p_x1, out, TOK, DIM, HID);
}

// round 17
// speedup vs baseline: 1.0505x; 1.0505x over previous
#include <cuda_runtime.h>
#include <cuda_fp16.h>
#include <math.h>
#include <stdint.h>

#define TOK   4096
#define NSEQ  2048
#define DIM   768
#define H3    2304
#define HID   3072
#define NHEAD 12
#define HD    64

__device__ __align__(128) __half g_h  [TOK * DIM];
__device__ __align__(128) __half g_qkv[TOK * H3];
__device__ __align__(128) __half g_o  [TOK * DIM];
__device__ __align__(128) float  g_x1 [TOK * DIM];
__device__ __align__(128) __half g_h2 [TOK * DIM];
__device__ __align__(128) __half g_m  [TOK * HID];
__device__ __align__(128) __half g_wq [H3 * DIM];
__device__ __align__(128) __half g_wp [DIM * DIM];
__device__ __align__(128) __half g_w1 [HID * DIM];
__device__ __align__(128) __half g_w2 [DIM * HID];

// ---------------- PTX helpers ----------------
__device__ __forceinline__ void mma_f16(float* d,
    uint32_t a0, uint32_t a1, uint32_t a2, uint32_t a3, uint32_t b0, uint32_t b1)
{
    asm volatile(
        "mma.sync.aligned.m16n8k16.row.col.f32.f16.f16.f32 "
        "{%0,%1,%2,%3}, {%4,%5,%6,%7}, {%8,%9}, {%0,%1,%2,%3};"
        : "+f"(d[0]), "+f"(d[1]), "+f"(d[2]), "+f"(d[3])
        : "r"(a0), "r"(a1), "r"(a2), "r"(a3), "r"(b0), "r"(b1));
}
__device__ __forceinline__ void cp_async16(uint32_t s, const void* g) {
    asm volatile("cp.async.cg.shared.global [%0], [%1], 16;" :: "r"(s), "l"(g));
}
__device__ __forceinline__ void cp_commit() { asm volatile("cp.async.commit_group;" ::); }
template<int N> __device__ __forceinline__ void cp_wait() {
    asm volatile("cp.async.wait_group %0;" :: "n"(N));
}
__device__ __forceinline__ uint32_t smem_u32(const void* p) {
    uint32_t a;
    asm("{ .reg .u64 t; cvta.to.shared.u64 t, %1; cvt.u32.u64 %0, t; }" : "=r"(a) : "l"(p));
    return a;
}
__device__ __forceinline__ uint32_t h2u(float x, float y) {
    __half2 h = __floats2half2_rn(x, y);
    return *(uint32_t*)&h;
}
__device__ __forceinline__ float ex2(float x) {
    float y; asm("ex2.approx.f32 %0, %1;" : "=f"(y) : "f"(x)); return y;
}
__device__ __forceinline__ void ldsm_x4(
    uint32_t& r0, uint32_t& r1, uint32_t& r2, uint32_t& r3, uint32_t a)
{
    asm volatile("ldmatrix.sync.aligned.m8n8.x4.shared.b16 {%0,%1,%2,%3}, [%4];"
                 : "=r"(r0), "=r"(r1), "=r"(r2), "=r"(r3) : "r"(a));
}
__device__ __forceinline__ void ldsm_x4_t(
    uint32_t& r0, uint32_t& r1, uint32_t& r2, uint32_t& r3, uint32_t a)
{
    asm volatile("ldmatrix.sync.aligned.m8n8.x4.trans.shared.b16 {%0,%1,%2,%3}, [%4];"
                 : "=r"(r0), "=r"(r1), "=r"(r2), "=r"(r3) : "r"(a));
}

// -------- merged preamble: weight transpose (4 weights) + LN1, one launch --------
#define TRW_B0 (72 * 24)
#define TRW_B1 (24 * 24)
#define TRW_B2 (96 * 24)
#define TRW_B3 (24 * 96)
#define TRW_TOTAL (TRW_B0 + TRW_B1 + TRW_B2 + TRW_B3)
#define PRE_TOTAL (TRW_TOTAL + TOK)

__global__ __launch_bounds__(256) void preamble_kernel(
    const float* __restrict__ s0, __half* __restrict__ d0,
    const float* __restrict__ s1, __half* __restrict__ d1,
    const float* __restrict__ s2, __half* __restrict__ d2,
    const float* __restrict__ s3, __half* __restrict__ d3,
    const float* __restrict__ x,  const float* __restrict__ lg,
    const float* __restrict__ lb, __half* __restrict__ lout)
{
    int blk = blockIdx.x;
    if (blk >= TRW_TOTAL) {
        int row = blk - TRW_TOTAL, t = threadIdx.x;
        const float* xr = x + row * DIM;
        float v0 = xr[t], v1 = xr[t + 256], v2 = xr[t + 512];
        float s = v0 + v1 + v2, q = v0 * v0 + v1 * v1 + v2 * v2;
        __shared__ float rs[8], rq[8];
        #pragma unroll
        for (int o = 16; o; o >>= 1) {
            s += __shfl_xor_sync(0xffffffffu, s, o);
            q += __shfl_xor_sync(0xffffffffu, q, o);
        }
        if ((t & 31) == 0) { rs[t >> 5] = s; rq[t >> 5] = q; }
        __syncthreads();
        __shared__ float smu, srstd;
        if (t == 0) {
            float S = 0.f, Q = 0.f;
            #pragma unroll
            for (int i = 0; i < 8; i++) { S += rs[i]; Q += rq[i]; }
            float mu = S * (1.0f / DIM), var = Q * (1.0f / DIM) - mu * mu;
            smu = mu; srstd = rsqrtf(var + 1e-5f);
        }
        __syncthreads();
        float mu = smu, r = srstd;
        __half* orow = lout + row * DIM;
        orow[t]       = __float2half((v0 - mu) * r * lg[t]       + lb[t]);
        orow[t + 256] = __float2half((v1 - mu) * r * lg[t + 256] + lb[t + 256]);
        orow[t + 512] = __float2half((v2 - mu) * r * lg[t + 512] + lb[t + 512]);
        return;
    }
    const float* src; __half* dst; int K, N, lbk;
    if (blk < TRW_B0)                       { src = s0; dst = d0; K = DIM; N = H3;  lbk = blk; }
    else if (blk < TRW_B0 + TRW_B1)         { src = s1; dst = d1; K = DIM; N = DIM; lbk = blk - TRW_B0; }
    else if (blk < TRW_B0 + TRW_B1 + TRW_B2){ src = s2; dst = d2; K = DIM; N = HID; lbk = blk - TRW_B0 - TRW_B1; }
    else                                    { src = s3; dst = d3; K = HID; N = DIM; lbk = blk - TRW_B0 - TRW_B1 - TRW_B2; }
    int nblk = N / 32;
    int nb = (lbk % nblk) * 32, kb = (lbk / nblk) * 32;

    __shared__ float t[32][33];
    int tx = threadIdx.x & 31, ty = threadIdx.x >> 5;
    #pragma unroll
    for (int i = 0; i < 32; i += 8)
        t[ty + i][tx] = src[(size_t)(kb + ty + i) * N + nb + tx];
    __syncthreads();
    #pragma unroll
    for (int i = 0; i < 32; i += 8)
        dst[(size_t)(nb + ty + i) * K + kb + tx] = __float2half(t[tx][ty + i]);
}

// -------- LayerNorm, warp-per-row (8 rows/CTA) --------
__global__ __launch_bounds__(256) void ln_kernel(
    const float* __restrict__ x, const float* __restrict__ g,
    const float* __restrict__ b, __half* __restrict__ out)
{
    int warp = threadIdx.x >> 5, lane = threadIdx.x & 31;
    int row = blockIdx.x * 8 + warp;
    const float4* xr = (const float4*)(x + (size_t)row * DIM);

    float4 v[6];
    float s = 0.f, q = 0.f;
    #pragma unroll
    for (int i = 0; i < 6; i++) {
        v[i] = xr[lane + i * 32];
        s += v[i].x + v[i].y + v[i].z + v[i].w;
        q += v[i].x * v[i].x + v[i].y * v[i].y + v[i].z * v[i].z + v[i].w * v[i].w;
    }
    #pragma unroll
    for (int o = 16; o; o >>= 1) {
        s += __shfl_xor_sync(0xffffffffu, s, o);
        q += __shfl_xor_sync(0xffffffffu, q, o);
    }
    float mu = s * (1.0f / DIM);
    float r  = rsqrtf(q * (1.0f / DIM) - mu * mu + 1e-5f);

    __half* orow = out + (size_t)row * DIM;
    #pragma unroll
    for (int i = 0; i < 6; i++) {
        int c = (lane + i * 32) * 4;
        const float4 gg = *(const float4*)&g[c];
        const float4 bb = *(const float4*)&b[c];
        *(__half2*)&orow[c] = __floats2half2_rn(
            (v[i].x - mu) * r * gg.x + bb.x, (v[i].y - mu) * r * gg.y + bb.y);
        *(__half2*)&orow[c + 2] = __floats2half2_rn(
            (v[i].z - mu) * r * gg.z + bb.z, (v[i].w - mu) * r * gg.w + bb.w);
    }
}

// -------- fp16 tensor-core GEMM: C = A[M,K] @ BT[N,K]^T (+epilogue) --------
// BM x BN CTA tile, 128 threads = 4 warps (2x2), warp tile (BM/2) x (BN/2).
// ldmatrix.x4 fetch, 4-stage cp.async pipeline.
#define HST 40
#define HSTAGES 4
#define HSMEM_OF(BM, BN) (HSTAGES * ((BM) + (BN)) * HST * 2)

template<int EPI, typename OT, int BM, int BN>
__global__ __launch_bounds__(128) void gemm_h(
    const __half* __restrict__ A, const __half* __restrict__ BT,
    const float* __restrict__ bias, const float* __restrict__ res,
    OT* __restrict__ C, int M, int N, int K)
{
    constexpr int MI = BM / 32;
    constexpr int NF = BN / 16;
    constexpr int ATILE_B = BM * HST * 2;
    constexpr int BTILE_B = BN * HST * 2;
    constexpr int STAGE_B = ATILE_B + BTILE_B;

    extern __shared__ char smem[];
    uint32_t sb = smem_u32(smem);

    int tid = threadIdx.x, lane = tid & 31, warp = tid >> 5;
    int wm = warp >> 1, wn = warp & 1;
    int gq = lane >> 2, gt = lane & 3;
    int row0 = blockIdx.y * BM, col0 = blockIdx.x * BN;

    int lrow = lane & 7;
    int lmid = (lane >> 3) & 1;
    int lhi  = lane >> 4;
    int a_row = lrow + 8 * lmid;
    int a_c8  = lhi;
    int b_row = lrow + 8 * lhi;
    int b_c8  = lmid;

    float acc[MI][NF][4];
    #pragma unroll
    for (int mi = 0; mi < MI; mi++)
        #pragma unroll
        for (int nf = 0; nf < NF; nf++)
            #pragma unroll
            for (int j = 0; j < 4; j++) acc[mi][nf][j] = 0.f;

    auto load_tile = [&](int kt, int buf) {
        uint32_t ab = sb + buf * STAGE_B;
        int k0 = kt * 32;
        #pragma unroll
        for (int i = 0; i < BM / 32; i++) {
            int e = tid + i * 128;
            int r = e >> 2, c8 = e & 3;
            cp_async16(ab + r * (HST * 2) + c8 * 16,
                       A + (size_t)(row0 + r) * K + k0 + c8 * 8);
        }
        #pragma unroll
        for (int i = 0; i < BN / 32; i++) {
            int e = tid + i * 128;
            int r = e >> 2, c8 = e & 3;
            cp_async16(ab + ATILE_B + r * (HST * 2) + c8 * 16,
                       BT + (size_t)(col0 + r) * K + k0 + c8 * 8);
        }
        cp_commit();
    };

    int nt = K / 32;
    load_tile(0, 0);
    load_tile(1, 1);
    load_tile(2, 2);

    for (int t = 0; t < nt; t++) {
        cp_wait<HSTAGES - 2>();
        __syncthreads();
        if (t + 3 < nt) load_tile(t + 3, (t + 3) % HSTAGES);
        int buf = t % HSTAGES;

        uint32_t Ab = sb + buf * STAGE_B;
        uint32_t Bb = Ab + ATILE_B;

        #pragma unroll
        for (int ks = 0; ks < 2; ks++) {
            int kh = ks * 16;
            uint32_t af[MI][4];
            #pragma unroll
            for (int mi = 0; mi < MI; mi++) {
                uint32_t addr = Ab + ((wm * (BM / 2) + mi * 16 + a_row) * HST + kh + a_c8 * 8) * 2;
                ldsm_x4(af[mi][0], af[mi][1], af[mi][2], af[mi][3], addr);
            }
            uint32_t bf[NF][2];
            #pragma unroll
            for (int p = 0; p < NF / 2; p++) {
                uint32_t addr = Bb + ((wn * (BN / 2) + p * 16 + b_row) * HST + kh + b_c8 * 8) * 2;
                ldsm_x4(bf[2 * p][0], bf[2 * p][1], bf[2 * p + 1][0], bf[2 * p + 1][1], addr);
            }
            #pragma unroll
            for (int mi = 0; mi < MI; mi++)
                #pragma unroll
                for (int nf = 0; nf < NF; nf++)
                    mma_f16(acc[mi][nf],
                            af[mi][0], af[mi][1], af[mi][2], af[mi][3],
                            bf[nf][0], bf[nf][1]);
        }
    }

    #pragma unroll
    for (int mi = 0; mi < MI; mi++) {
        int r = row0 + wm * (BM / 2) + mi * 16 + gq;
        #pragma unroll
        for (int nf = 0; nf < NF; nf++) {
            int c = col0 + wn * (BN / 2) + nf * 8 + gt * 2;
            float v0 = acc[mi][nf][0], v1 = acc[mi][nf][1];
            float v2 = acc[mi][nf][2], v3 = acc[mi][nf][3];
            if (EPI >= 1) {
                float b0 = bias[c], b1 = bias[c + 1];
                v0 += b0; v1 += b1; v2 += b0; v3 += b1;
            }
            if (EPI == 1) {
                const float2 r01 = *(const float2*)&res[(size_t) r      * N + c];
                const float2 r23 = *(const float2*)&res[(size_t)(r + 8) * N + c];
                v0 += r01.x; v1 += r01.y; v2 += r23.x; v3 += r23.y;
            }
            if (EPI == 2) {
                v0 = 0.5f * v0 * (1.0f + erff(v0 * 0.70710678118f));
                v1 = 0.5f * v1 * (1.0f + erff(v1 * 0.70710678118f));
                v2 = 0.5f * v2 * (1.0f + erff(v2 * 0.70710678118f));
                v3 = 0.5f * v3 * (1.0f + erff(v3 * 0.70710678118f));
            }
            if constexpr (sizeof(OT) == 2) {
                __half* Ch = (__half*)C;
                *(__half2*)&Ch[(size_t) r      * N + c] = __floats2half2_rn(v0, v1);
                *(__half2*)&Ch[(size_t)(r + 8) * N + c] = __floats2half2_rn(v2, v3);
            } else {
                float* Cf = (float*)C;
                *(float2*)&Cf[(size_t) r      * N + c] = make_float2(v0, v1);
                *(float2*)&Cf[(size_t)(r + 8) * N + c] = make_float2(v2, v3);
            }
        }
    }
}

// -------- fp16 flash attention (unchanged from R15) --------
#define KVH (64 * 72)
#define QHS (128 * 72)
#define ATTN_SMEM_B ((QHS + 6 * KVH) * 2)

__global__ __launch_bounds__(256) void attn_h(
    const __half* __restrict__ qkv, __half* __restrict__ o)
{
    extern __shared__ __half smh[];
    __half* Qs = smh;
    __half* Ks = smh + QHS;
    __half* Vs = smh + QHS + 3 * KVH;

    int tid = threadIdx.x, lane = tid & 31, warp = tid >> 5;
    int gq = lane >> 2, gt = lane & 3, wr = warp * 16;
    int lrow = lane & 7, lsel = (lane >> 3) & 1, lhi = lane >> 4;
    int qt = blockIdx.x, h = blockIdx.y, b = blockIdx.z;
    int q_tok0 = b * NSEQ + qt * 128;
    int qcol = h * HD, kcol = DIM + h * HD, vcol = 2 * DIM + h * HD;

    auto load_kv = [&](int kt, int buf) {
        int k_tok0 = b * NSEQ + kt * 64;
        #pragma unroll
        for (int i = 0; i < 2; i++) {
            int e = tid + i * 256;
            int r = e >> 3, c = e & 7;
            cp_async16(smem_u32(&Ks[buf * KVH + r * 72 + c * 8]),
                       qkv + (size_t)(k_tok0 + r) * H3 + kcol + c * 8);
            cp_async16(smem_u32(&Vs[buf * KVH + r * 72 + c * 8]),
                       qkv + (size_t)(k_tok0 + r) * H3 + vcol + c * 8);
        }
        cp_commit();
    };

    #pragma unroll
    for (int i = 0; i < 4; i++) {
        int e = tid + i * 256;
        int r = e >> 3, c = e & 7;
        cp_async16(smem_u32(&Qs[r * 72 + c * 8]),
                   qkv + (size_t)(q_tok0 + r) * H3 + qcol + c * 8);
    }
    cp_commit();
    load_kv(0, 0);
    cp_wait<1>();
    __syncthreads();

    const uint32_t* Qu = (const uint32_t*)Qs;
    __half2 hs = __half2half2(__float2half(0.125f * 1.44269504f));
    uint32_t qf[4][4];
    #pragma unroll
    for (int ks = 0; ks < 4; ks++) {
        #pragma unroll
        for (int j = 0; j < 4; j++) {
            int r = wr + gq + (j & 1) * 8;
            int cw = 8 * ks + gt + (j >> 1) * 4;
            __half2 v = *(__half2*)&Qu[r * 36 + cw];
            v = __hmul2(v, hs);
            qf[ks][j] = *(uint32_t*)&v;
        }
    }
    load_kv(1, 1);

    uint32_t kbase[4], vbase[4];
    #pragma unroll
    for (int p = 0; p < 4; p++) {
        kbase[p] = smem_u32(&Ks[(p * 16 + lhi * 8 + lrow) * 72 + lsel * 8]);
        vbase[p] = smem_u32(&Vs[(lsel * 8 + lrow) * 72 + p * 16 + lhi * 8]);
    }

    float m0 = -1e30f, m1 = -1e30f, l0 = 0.f, l1 = 0.f;
    float oacc[8][4];
    #pragma unroll
    for (int nf = 0; nf < 8; nf++)
        #pragma unroll
        for (int j = 0; j < 4; j++) oacc[nf][j] = 0.f;

    const int nkt = NSEQ / 64;
    for (int kt = 0; kt < nkt; kt++) {
        cp_wait<1>();
        __syncthreads();
        if (kt + 2 < nkt) load_kv(kt + 2, (kt + 2) % 3);
        uint32_t boff = (uint32_t)((kt % 3) * KVH * 2);

        float sacc[8][4];
        #pragma unroll
        for (int nf = 0; nf < 8; nf++)
            #pragma unroll
            for (int j = 0; j < 4; j++) sacc[nf][j] = 0.f;
        #pragma unroll
        for (int ks = 0; ks < 4; ks++) {
            #pragma unroll
            for (int nfp = 0; nfp < 4; nfp++) {
                uint32_t b0, b1, b2, b3;
                ldsm_x4(b0, b1, b2, b3, kbase[nfp] + boff + ks * 32);
                mma_f16(sacc[2 * nfp],     qf[ks][0], qf[ks][1], qf[ks][2], qf[ks][3], b0, b1);
                mma_f16(sacc[2 * nfp + 1], qf[ks][0], qf[ks][1], qf[ks][2], qf[ks][3], b2, b3);
            }
        }

        float mx0 = -1e30f, mx1 = -1e30f;
        #pragma unroll
        for (int nf = 0; nf < 8; nf++) {
            mx0 = fmaxf(mx0, fmaxf(sacc[nf][0], sacc[nf][1]));
            mx1 = fmaxf(mx1, fmaxf(sacc[nf][2], sacc[nf][3]));
        }
        mx0 = fmaxf(mx0, __shfl_xor_sync(0xffffffffu, mx0, 1));
        mx0 = fmaxf(mx0, __shfl_xor_sync(0xffffffffu, mx0, 2));
        mx1 = fmaxf(mx1, __shfl_xor_sync(0xffffffffu, mx1, 1));
        mx1 = fmaxf(mx1, __shfl_xor_sync(0xffffffffu, mx1, 2));
        float mn0 = fmaxf(m0, mx0), mn1 = fmaxf(m1, mx1);
        float alpha0 = ex2(m0 - mn0), alpha1 = ex2(m1 - mn1);
        m0 = mn0; m1 = mn1;

        float sum0 = 0.f, sum1 = 0.f;
        #pragma unroll
        for (int nf = 0; nf < 8; nf++) {
            sacc[nf][0] = ex2(sacc[nf][0] - mn0);
            sacc[nf][1] = ex2(sacc[nf][1] - mn0);
            sacc[nf][2] = ex2(sacc[nf][2] - mn1);
            sacc[nf][3] = ex2(sacc[nf][3] - mn1);
            sum0 += sacc[nf][0] + sacc[nf][1];
            sum1 += sacc[nf][2] + sacc[nf][3];
        }
        sum0 += __shfl_xor_sync(0xffffffffu, sum0, 1);
        sum0 += __shfl_xor_sync(0xffffffffu, sum0, 2);
        sum1 += __shfl_xor_sync(0xffffffffu, sum1, 1);
        sum1 += __shfl_xor_sync(0xffffffffu, sum1, 2);
        l0 = l0 * alpha0 + sum0;
        l1 = l1 * alpha1 + sum1;

        if (!__all_sync(0xffffffffu, (alpha0 == 1.0f) & (alpha1 == 1.0f))) {
            #pragma unroll
            for (int nf = 0; nf < 8; nf++) {
                oacc[nf][0] *= alpha0; oacc[nf][1] *= alpha0;
                oacc[nf][2] *= alpha1; oacc[nf][3] *= alpha1;
            }
        }

        #pragma unroll
        for (int j = 0; j < 4; j++) {
            uint32_t a0 = h2u(sacc[2 * j    ][0], sacc[2 * j    ][1]);
            uint32_t a1 = h2u(sacc[2 * j    ][2], sacc[2 * j    ][3]);
            uint32_t a2 = h2u(sacc[2 * j + 1][0], sacc[2 * j + 1][1]);
            uint32_t a3 = h2u(sacc[2 * j + 1][2], sacc[2 * j + 1][3]);
            #pragma unroll
            for (int nfp = 0; nfp < 4; nfp++) {
                uint32_t b0, b1, b2, b3;
                ldsm_x4_t(b0, b1, b2, b3, vbase[nfp] + boff + j * 2304);
                mma_f16(oacc[2 * nfp],     a0, a1, a2, a3, b0, b1);
                mma_f16(oacc[2 * nfp + 1], a0, a1, a2, a3, b2, b3);
            }
        }
    }

    float invl0 = 1.0f / l0, invl1 = 1.0f / l1;
    int r0 = q_tok0 + wr + gq;
    #pragma unroll
    for (int nf = 0; nf < 8; nf++) {
        int c = h * HD + nf * 8 + gt * 2;
        *(__half2*)&o[(size_t) r0      * DIM + c] =
            __floats2half2_rn(oacc[nf][0] * invl0, oacc[nf][1] * invl0);
        *(__half2*)&o[(size_t)(r0 + 8) * DIM + c] =
            __floats2half2_rn(oacc[nf][2] * invl1, oacc[nf][3] * invl1);
    }
}

// ---------------- Launch ----------------
extern "C" void kernel_launch(void* const* d_in, const int* in_sizes, int n_in,
                              void* d_out, int out_size)
{
    const float* x      = (const float*)d_in[0];
    const float* ln1_g  = (const float*)d_in[1];
    const float* ln1_b  = (const float*)d_in[2];
    const float* w_qkv  = (const float*)d_in[3];
    const float* w_proj = (const float*)d_in[4];
    const float* b_proj = (const float*)d_in[5];
    const float* ln2_g  = (const float*)d_in[6];
    const float* ln2_b  = (const float*)d_in[7];
    const float* w_fc1  = (const float*)d_in[8];
    const float* b_fc1  = (const float*)d_in[9];
    const float* w_fc2  = (const float*)d_in[10];
    const float* b_fc2  = (const float*)d_in[11];
    float* out = (float*)d_out;

    __half *p_h, *p_qkv, *p_o, *p_h2, *p_m, *p_wq, *p_wp, *p_w1, *p_w2;
    float  *p_x1;
    cudaGetSymbolAddress((void**)&p_h,   g_h);
    cudaGetSymbolAddress((void**)&p_qkv, g_qkv);
    cudaGetSymbolAddress((void**)&p_o,   g_o);
    cudaGetSymbolAddress((void**)&p_x1,  g_x1);
    cudaGetSymbolAddress((void**)&p_h2,  g_h2);
    cudaGetSymbolAddress((void**)&p_m,   g_m);
    cudaGetSymbolAddress((void**)&p_wq,  g_wq);
    cudaGetSymbolAddress((void**)&p_wp,  g_wp);
    cudaGetSymbolAddress((void**)&p_w1,  g_w1);
    cudaGetSymbolAddress((void**)&p_w2,  g_w2);

    cudaFuncSetAttribute(attn_h, cudaFuncAttributeMaxDynamicSharedMemorySize, ATTN_SMEM_B);
    cudaFuncSetAttribute((gemm_h<0, __half, 128, 128>), cudaFuncAttributeMaxDynamicSharedMemorySize, HSMEM_OF(128, 128));
    cudaFuncSetAttribute((gemm_h<2, __half, 128, 128>), cudaFuncAttributeMaxDynamicSharedMemorySize, HSMEM_OF(128, 128));
    cudaFuncSetAttribute((gemm_h<1, float, 128, 64>),   cudaFuncAttributeMaxDynamicSharedMemorySize, HSMEM_OF(128, 64));

    // 0. preamble: weight transpose + LN1 (one launch)
    preamble_kernel<<<PRE_TOTAL, 256>>>(w_qkv, p_wq, w_proj, p_wp,
                                        w_fc1, p_w1, w_fc2, p_w2,
                                        x, ln1_g, ln1_b, p_h);
    // 2. QKV GEMM (128x128)
    gemm_h<0, __half, 128, 128><<<dim3(H3 / 128, TOK / 128), 128, HSMEM_OF(128, 128)>>>(
        p_h, p_wq, nullptr, nullptr, p_qkv, TOK, H3, DIM);
    // 3. Attention
    attn_h<<<dim3(NSEQ / 128, NHEAD, 2), 256, ATTN_SMEM_B>>>(p_qkv, p_o);
    // 4. Proj + bias + residual(x) -> fp32 (128x64)
    gemm_h<1, float, 128, 64><<<dim3(DIM / 64, TOK / 128), 128, HSMEM_OF(128, 64)>>>(
        p_o, p_wp, b_proj, x, p_x1, TOK, DIM, DIM);
    // 5. LN2 -> fp16 (warp-per-row)
    ln_kernel<<<TOK / 8, 256>>>(p_x1, ln2_g, ln2_b, p_h2);
    // 6. FC1 + bias + GELU -> fp16 (128x128)
    gemm_h<2, __half, 128, 128><<<dim3(HID / 128, TOK / 128), 128, HSMEM_OF(128, 128)>>>(
        p_h2, p_w1, b_fc1, nullptr, p_m, TOK, HID, DIM);
    // 7. FC2 + bias + residual(x1) -> out (128x64)
    gemm_h<1, float, 128, 64><<<dim3(DIM / 64, TOK / 128), 128, HSMEM_OF(128, 64)>>>(
        p_m, p_w2, b_fc2, p_x1, out, TOK, DIM, HID);
}